// round 10
// baseline (speedup 1.0000x reference)
#include <cuda_runtime.h>
#include <stdint.h>

// out[b][r] = prod_{i=0..7} v(b,i,mf[r][i]);  v = 1.0 if idx==-1 else x[b][i][idx]
// Pair tables (4 x 25 per batch). HYBRID gather: tables 0,1 in smem (LDS,
// 25-consecutive-word conflict-free), tables 2,3 in REGISTERS one-entry-
// per-lane, gathered via __shfl_sync (register crossbar, off the L1TEX
// pipe). Cuts L1 wavefronts per 1024 outputs from ~193 to ~129.
// Warp-autonomous: fixed 128-rule tile per warp, 8-batch groups, no block
// barriers. 1024 threads, 1 CTA/SM (reg cap 64 -> no spill; R8 lesson).

#define THREADS 1024
#define NBLK 148
#define NSTREAMS 296          // (148*32 warps) / 16 tiles

__global__ __launch_bounds__(THREADS, 1)
void fire_kernel(const float* __restrict__ x, const int* __restrict__ mf,
                 float* __restrict__ out, int n_rules, int n_groups) {
    extern __shared__ float ptab[];
    const int lane = threadIdx.x & 31;
    const int wid  = threadIdx.x >> 5;
    float* myp = ptab + wid * 416;          // 8 batches x 52 (tables 0,1)

    const int stream = wid * NBLK + (int)blockIdx.x;   // 0..4735
    const int tile   = stream & 15;
    const int g0     = stream >> 4;                    // 0..295
    const int r0     = tile << 7;

    // ---- prologue: packed rule offsets. byte0=o0, byte1=25+o1, byte2=o2, byte3=o3
    uint32_t pk[4];
    {
        const int4* m4 = (const int4*)(mf + (size_t)(r0 + 4 * lane) * 8);
#pragma unroll
        for (int q = 0; q < 4; ++q) {
            int4 lo = m4[2 * q + 0];
            int4 hi = m4[2 * q + 1];
            uint32_t o0 = (uint32_t)((lo.x + 1) * 5 + (lo.y + 1));
            uint32_t o1 = (uint32_t)(25 + (lo.z + 1) * 5 + (lo.w + 1));
            uint32_t o2 = (uint32_t)((hi.x + 1) * 5 + (hi.y + 1));
            uint32_t o3 = (uint32_t)((hi.z + 1) * 5 + (hi.w + 1));
            pk[q] = o0 | (o1 << 8) | (o2 << 16) | (o3 << 24);
        }
    }

    // smem-build mapping (lanes 0..15): batch bb = lane>>1, table pp = lane&1
    const int bb = lane >> 1, pp = lane & 1;
    // register-table entry mapping: entry = lane (lanes 0..24): a=entry/5, c=entry%5
    const int ea = lane / 5, ec = lane % 5;
    // shuffle-source x columns for tables 2 (inputs 4,5) and 3 (inputs 6,7)
    const int ia2 = 16 + (ea ? ea - 1 : 0), ic2 = 20 + (ec ? ec - 1 : 0);
    const int ia3 = 24 + (ea ? ea - 1 : 0), ic3 = 28 + (ec ? ec - 1 : 0);

    for (int g = g0; g < n_groups; g += NSTREAMS) {
        // ---- build smem tables 0,1 (16 lanes; STS bases 52*bb+25*pp distinct mod 32) ----
        if (lane < 16) {
            const float4* p4 = (const float4*)(x + (size_t)g * 256 + bb * 32 + pp * 8);
            float4 xa = p4[0];
            float4 xc = p4[1];
            float Av[5] = {1.0f, xa.x, xa.y, xa.z, xa.w};
            float Cv[5] = {1.0f, xc.x, xc.y, xc.z, xc.w};
            float* dst = myp + bb * 52 + pp * 25;
#pragma unroll
            for (int a = 0; a < 5; ++a)
#pragma unroll
                for (int c = 0; c < 5; ++c)
                    dst[a * 5 + c] = Av[a] * Cv[c];
        }

        // ---- build register tables 2,3 (lane = entry, via shuffles) ----
        float T2[8], T3[8];
#pragma unroll
        for (int b = 0; b < 8; ++b) {
            float xv = x[(size_t)g * 256 + b * 32 + lane];
            float A2 = __shfl_sync(0xffffffffu, xv, ia2);
            float C2 = __shfl_sync(0xffffffffu, xv, ic2);
            float A3 = __shfl_sync(0xffffffffu, xv, ia3);
            float C3 = __shfl_sync(0xffffffffu, xv, ic3);
            if (ea == 0) { A2 = 1.0f; A3 = 1.0f; }
            if (ec == 0) { C2 = 1.0f; C3 = 1.0f; }
            T2[b] = A2 * C2;
            T3[b] = A3 * C3;
        }
        __syncwarp();

        // ---- compute 8 batches x 4 rules/lane ----
        float* o = out + (size_t)(g * 8) * n_rules + r0 + 4 * lane;
        const float* pb = myp;
#pragma unroll
        for (int b = 0; b < 8; ++b) {
            float4 v;
            v.x = (pb[pk[0] & 255u] * pb[(pk[0] >> 8) & 255u]) *
                  (__shfl_sync(0xffffffffu, T2[b], (int)((pk[0] >> 16) & 255u)) *
                   __shfl_sync(0xffffffffu, T3[b], (int)(pk[0] >> 24)));
            v.y = (pb[pk[1] & 255u] * pb[(pk[1] >> 8) & 255u]) *
                  (__shfl_sync(0xffffffffu, T2[b], (int)((pk[1] >> 16) & 255u)) *
                   __shfl_sync(0xffffffffu, T3[b], (int)(pk[1] >> 24)));
            v.z = (pb[pk[2] & 255u] * pb[(pk[2] >> 8) & 255u]) *
                  (__shfl_sync(0xffffffffu, T2[b], (int)((pk[2] >> 16) & 255u)) *
                   __shfl_sync(0xffffffffu, T3[b], (int)(pk[2] >> 24)));
            v.w = (pb[pk[3] & 255u] * pb[(pk[3] >> 8) & 255u]) *
                  (__shfl_sync(0xffffffffu, T2[b], (int)((pk[3] >> 16) & 255u)) *
                   __shfl_sync(0xffffffffu, T3[b], (int)(pk[3] >> 24)));
            *(float4*)o = v;
            pb += 52;
            o  += n_rules;
        }
        __syncwarp();   // order LDS of this iter before next iter's STS rebuild
    }
}

extern "C" void kernel_launch(void* const* d_in, const int* in_sizes, int n_in,
                              void* d_out, int out_size) {
    const float* x  = (const float*)d_in[0];
    const int*   mf = (const int*)d_in[1];
    float* out = (float*)d_out;

    const int n_rules  = in_sizes[1] / 8;     // 2048
    const int B        = in_sizes[0] / 32;    // 8192
    const int n_groups = B / 8;               // 1024

    size_t smem = 32 * 416 * sizeof(float);   // 53.2 KB
    cudaFuncSetAttribute(fire_kernel, cudaFuncAttributeMaxDynamicSharedMemorySize, (int)smem);
    fire_kernel<<<NBLK, THREADS, smem>>>(x, mf, out, n_rules, n_groups);
}

// round 11
// speedup vs baseline: 1.0834x; 1.0834x over previous
#include <cuda_runtime.h>
#include <stdint.h>

// out[b][r] = prod_{i=0..7} v(b,i,mf[r][i]);  v = 1.0 if idx==-1 else x[b][i][idx]
// Pair tables (4 x 25 per batch) in per-warp smem, warp-autonomous streams,
// conflict-free STS build (100b+25p+e bijective mod 32) and conflict-free
// gathers (25 consecutive words per table). NEW: software-pipelined inner
// loop — prefetch batch b+1's 16 table values into registers while batch b
// multiplies/stores, so the LSU pipe never idles between LDS bursts.

#define THREADS 1024
#define NBLK 148
#define NSTREAMS 296          // (148*32 warps) / 16 tiles

__global__ __launch_bounds__(THREADS, 1)
void fire_kernel(const float* __restrict__ x, const int* __restrict__ mf,
                 float* __restrict__ out, int n_rules, int n_groups) {
    extern __shared__ float ptab[];
    const int lane = threadIdx.x & 31;
    const int wid  = threadIdx.x >> 5;
    float* myp = ptab + wid * 800;          // 8 batches x stride 100

    const int stream = wid * NBLK + (int)blockIdx.x;   // 0..4735
    const int tile   = stream & 15;
    const int g0     = stream >> 4;                    // 0..295
    const int r0     = tile << 7;

    // ---- prologue: 16 table byte-offsets for this lane's 4 rules ----
    // rule q component p -> table p entry, pre-scaled by 4 (byte offset),
    // table p base 25*p included.
    int boff[16];
    {
        const int4* m4 = (const int4*)(mf + (size_t)(r0 + 4 * lane) * 8);
#pragma unroll
        for (int q = 0; q < 4; ++q) {
            int4 lo = m4[2 * q + 0];
            int4 hi = m4[2 * q + 1];
            boff[q * 4 + 0] = 4 * (((lo.x + 1) * 5 + (lo.y + 1)));
            boff[q * 4 + 1] = 4 * (25 + (lo.z + 1) * 5 + (lo.w + 1));
            boff[q * 4 + 2] = 4 * (50 + (hi.x + 1) * 5 + (hi.y + 1));
            boff[q * 4 + 3] = 4 * (75 + (hi.z + 1) * 5 + (hi.w + 1));
        }
    }

    // build mapping: all 32 lanes; batch slot = lane>>2, pair = lane&3
    const int bslot = lane >> 2;
    const int pslot = lane & 3;
    const size_t xoff = (size_t)bslot * 32 + pslot * 8;

    for (int g = g0; g < n_groups; g += NSTREAMS) {
        // ---- build tables for this 8-batch group (conflict-free STS) ----
        {
            const float4* p4 = (const float4*)(x + (size_t)g * 256 + xoff);
            float4 xa = p4[0];
            float4 xc = p4[1];
            float Av[5] = {1.0f, xa.x, xa.y, xa.z, xa.w};
            float Cv[5] = {1.0f, xc.x, xc.y, xc.z, xc.w};
            float* dst = myp + bslot * 100 + pslot * 25;
#pragma unroll
            for (int a = 0; a < 5; ++a)
#pragma unroll
                for (int c = 0; c < 5; ++c)
                    dst[a * 5 + c] = Av[a] * Cv[c];
        }
        __syncwarp();

        // ---- software-pipelined compute: 8 batches x 4 rules/lane ----
        const char* pb = (const char*)myp;
        float* o = out + (size_t)(g * 8) * n_rules + r0 + 4 * lane;

        float nxt[16];
#pragma unroll
        for (int j = 0; j < 16; ++j)
            nxt[j] = *(const float*)(pb + boff[j]);

#pragma unroll
        for (int b = 0; b < 8; ++b) {
            float cur[16];
#pragma unroll
            for (int j = 0; j < 16; ++j) cur[j] = nxt[j];

            if (b < 7) {
                const char* pn = pb + 400;   // next batch's tables
#pragma unroll
                for (int j = 0; j < 16; ++j)
                    nxt[j] = *(const float*)(pn + boff[j]);
            }

            float4 v;
            v.x = (cur[0]  * cur[1])  * (cur[2]  * cur[3]);
            v.y = (cur[4]  * cur[5])  * (cur[6]  * cur[7]);
            v.z = (cur[8]  * cur[9])  * (cur[10] * cur[11]);
            v.w = (cur[12] * cur[13]) * (cur[14] * cur[15]);
            *(float4*)o = v;

            pb += 400;          // 100 floats
            o  += n_rules;
        }
        __syncwarp();   // order this iter's LDS before next iter's rebuild
    }
}

extern "C" void kernel_launch(void* const* d_in, const int* in_sizes, int n_in,
                              void* d_out, int out_size) {
    const float* x  = (const float*)d_in[0];
    const int*   mf = (const int*)d_in[1];
    float* out = (float*)d_out;

    const int n_rules  = in_sizes[1] / 8;     // 2048
    const int B        = in_sizes[0] / 32;    // 8192
    const int n_groups = B / 8;               // 1024

    size_t smem = 32 * 800 * sizeof(float);   // 102.4 KB
    cudaFuncSetAttribute(fire_kernel, cudaFuncAttributeMaxDynamicSharedMemorySize, (int)smem);
    fire_kernel<<<NBLK, THREADS, smem>>>(x, mf, out, n_rules, n_groups);
}